// round 4
// baseline (speedup 1.0000x reference)
#include <cuda_runtime.h>

#define NE 2000
#define NB 8
#define NHID 256
#define ALPHA 0.2f
#define MASKF 9e-15f
#define L2E 1.4426950408889634f
#define KM (NE * 3)          // 6000

// Device scratch (no allocations allowed)
__device__ float g_s2[NE];
__device__ float g_h0[NE];
__device__ float g_h1[NE];
__device__ float g_h2[NE];
__device__ float g_s1[NE];
__device__ float g_x[NB * KM];   // elu(h_prime) flattened [b][i*3+d]

__device__ __forceinline__ float ex2f(float x) {
    float y;
    asm("ex2.approx.ftz.f32 %0, %1;" : "=f"(y) : "f"(x));
    return y;
}

// ---------------- Kernel A: h = emb @ W ; s1 = h@a[:3] ; s2 = h@a[3:] ----------------
// 4 rows per warp, 8 lanes per row, 2x LDG.128 per lane (MLP=2). grid=63.
__global__ __launch_bounds__(256) void kA(const float* __restrict__ emb,
                                          const float* __restrict__ W,
                                          const float* __restrict__ a) {
    __shared__ float Ws[64 * 3];
    __shared__ float as[6];
    int tid = threadIdx.x;
    if (tid < 192) Ws[tid] = W[tid];
    if (tid < 6)   as[tid] = a[tid];
    __syncthreads();

    int wid = tid >> 5;
    int lane = tid & 31;
    int r0 = (blockIdx.x * 8 + wid) * 4;       // first of 4 rows for this warp
    if (r0 >= NE) return;

    int r = r0 + (lane >> 3);                  // this lane's row
    int c4 = (lane & 7);                       // float4 index 0..7 (first half)

    const float4* er = reinterpret_cast<const float4*>(emb + (size_t)r * 64);
    float4 v0 = er[c4];
    float4 v1 = er[c4 + 8];

    float h0 = 0.f, h1 = 0.f, h2 = 0.f;
    int c0 = c4 * 4;
#pragma unroll
    for (int u = 0; u < 4; u++) {
        float e0 = (&v0.x)[u];
        float e1 = (&v1.x)[u];
        int ca = c0 + u, cb = c0 + 32 + u;
        h0 = fmaf(e0, Ws[ca * 3 + 0], fmaf(e1, Ws[cb * 3 + 0], h0));
        h1 = fmaf(e0, Ws[ca * 3 + 1], fmaf(e1, Ws[cb * 3 + 1], h1));
        h2 = fmaf(e0, Ws[ca * 3 + 2], fmaf(e1, Ws[cb * 3 + 2], h2));
    }
    // reduce across the 8 lanes of this row
#pragma unroll
    for (int o = 4; o; o >>= 1) {
        h0 += __shfl_xor_sync(~0u, h0, o);
        h1 += __shfl_xor_sync(~0u, h1, o);
        h2 += __shfl_xor_sync(~0u, h2, o);
    }
    if ((lane & 7) == 0) {
        g_h0[r] = h0; g_h1[r] = h1; g_h2[r] = h2;
        g_s1[r] = h0 * as[0] + h1 * as[1] + h2 * as[2];
        g_s2[r] = h0 * as[3] + h1 * as[4] + h2 * as[5];
    }
}

// ---------------- Kernel B: masked softmax + aggregation + ELU ----------------
// 125 CTAs x 8 warps, ONE balanced wave; each warp processes rows i0 and i0+1000,
// reusing the staged tables. Streams 128MB of adj exactly once.
__global__ __launch_bounds__(256) void kB(const int* __restrict__ adj) {
    __shared__ float ss2[NE];
    __shared__ float sh0[NE];
    __shared__ float sh1[NE];
    __shared__ float sh2[NE];
    __shared__ float redbuf[8];

    int tid = threadIdx.x;
    int lane = tid & 31;
    int wid = tid >> 5;

    // Stage tables (float4) + block max of s2
    float mx = -1e30f;
    {
        const float4* p2 = reinterpret_cast<const float4*>(g_s2);
        const float4* p0 = reinterpret_cast<const float4*>(g_h0);
        const float4* p1 = reinterpret_cast<const float4*>(g_h1);
        const float4* p3 = reinterpret_cast<const float4*>(g_h2);
        float4* q2 = reinterpret_cast<float4*>(ss2);
        float4* q0 = reinterpret_cast<float4*>(sh0);
        float4* q1 = reinterpret_cast<float4*>(sh1);
        float4* q3 = reinterpret_cast<float4*>(sh2);
        for (int q = tid; q < NE / 4; q += 256) {
            float4 v2 = p2[q];
            q2[q] = v2;
            q0[q] = p0[q];
            q1[q] = p1[q];
            q3[q] = p3[q];
            mx = fmaxf(fmaxf(fmaxf(mx, v2.x), fmaxf(v2.y, v2.z)), v2.w);
        }
    }
#pragma unroll
    for (int o = 16; o; o >>= 1) mx = fmaxf(mx, __shfl_xor_sync(~0u, mx, o));
    if (lane == 0) redbuf[wid] = mx;
    __syncthreads();
    float s2max = redbuf[0];
#pragma unroll
    for (int w = 1; w < 8; w++) s2max = fmaxf(s2max, redbuf[w]);

    int i0 = blockIdx.x * 8 + wid;     // 0..999; second row is i0+1000

#define PROC_K(COMP) do {                                                    \
        float t  = s1i + s2v.COMP;                                           \
        float e  = fmaxf(t, ALPHA * t);                                      \
        float wf = ex2f(fmaf(e, L2E, negc));                                 \
        float hj0 = h0v.COMP, hj1 = h1v.COMP, hj2 = h2v.COMP;                \
        _Pragma("unroll")                                                    \
        for (int b = 0; b < 8; b++) {                                        \
            float w = (av[b].COMP != 0) ? wf : w0;                           \
            Zb[b] += w;                                                      \
            A0[b] = fmaf(w, hj0, A0[b]);                                     \
            A1[b] = fmaf(w, hj1, A1[b]);                                     \
            A2[b] = fmaf(w, hj2, A2[b]);                                     \
        }                                                                    \
    } while (0)

#pragma unroll 1
    for (int ii = 0; ii < 2; ii++) {
        int i = i0 + ii * 1000;
        float s1i = g_s1[i];
        float ts = s1i + s2max;
        float c = fmaxf(fmaxf(ts, ALPHA * ts), MASKF);   // valid softmax shift
        float negc = -c * L2E;
        float w0 = ex2f(fmaf(MASKF, L2E, negc));         // weight of masked entries

        const int* base = adj + (size_t)i * NE;          // + b*NE*NE per batch

        float Zb[8], A0[8], A1[8], A2[8];
#pragma unroll
        for (int b = 0; b < 8; b++) { Zb[b] = 0.f; A0[b] = 0.f; A1[b] = 0.f; A2[b] = 0.f; }

        // 15 full iterations (no guard in hot loop)
#pragma unroll 2
        for (int it = 0; it < 15; it++) {
            int j0 = it * 128 + lane * 4;
            int4 av[8];
#pragma unroll
            for (int b = 0; b < 8; b++)
                av[b] = __ldcs(reinterpret_cast<const int4*>(base + (size_t)b * NE * NE + j0));
            float4 s2v = *reinterpret_cast<const float4*>(&ss2[j0]);
            float4 h0v = *reinterpret_cast<const float4*>(&sh0[j0]);
            float4 h1v = *reinterpret_cast<const float4*>(&sh1[j0]);
            float4 h2v = *reinterpret_cast<const float4*>(&sh2[j0]);
            PROC_K(x);
            PROC_K(y);
            PROC_K(z);
            PROC_K(w);
        }
        // Epilogue: j0 in [1920, 2000) -> lanes 0..19
        if (lane < 20) {
            int j0 = 1920 + lane * 4;
            int4 av[8];
#pragma unroll
            for (int b = 0; b < 8; b++)
                av[b] = __ldcs(reinterpret_cast<const int4*>(base + (size_t)b * NE * NE + j0));
            float4 s2v = *reinterpret_cast<const float4*>(&ss2[j0]);
            float4 h0v = *reinterpret_cast<const float4*>(&sh0[j0]);
            float4 h1v = *reinterpret_cast<const float4*>(&sh1[j0]);
            float4 h2v = *reinterpret_cast<const float4*>(&sh2[j0]);
            PROC_K(x);
            PROC_K(y);
            PROC_K(z);
            PROC_K(w);
        }

        // warp reductions (32 accumulators)
#pragma unroll
        for (int b = 0; b < 8; b++) {
#pragma unroll
            for (int o = 16; o; o >>= 1) {
                Zb[b] += __shfl_xor_sync(~0u, Zb[b], o);
                A0[b] += __shfl_xor_sync(~0u, A0[b], o);
                A1[b] += __shfl_xor_sync(~0u, A1[b], o);
                A2[b] += __shfl_xor_sync(~0u, A2[b], o);
            }
        }

        if (lane == 0) {
#pragma unroll
            for (int b = 0; b < 8; b++) {
                float inv = 1.0f / Zb[b];
                float p0 = A0[b] * inv;
                float p1 = A1[b] * inv;
                float p2 = A2[b] * inv;
                float x0 = (p0 > 0.f) ? p0 : expm1f(p0);
                float x1 = (p1 > 0.f) ? p1 : expm1f(p1);
                float x2 = (p2 > 0.f) ? p2 : expm1f(p2);
                float* xp = g_x + (size_t)b * KM + (size_t)i * 3;
                xp[0] = x0; xp[1] = x1; xp[2] = x2;
            }
        }
    }
#undef PROC_K
}

// ---------------- Kernel C: out[b,k] = x[b,:] . fc1_w[k,:] + fc1_b[k] ----------------
// Grid 128 (one wave): each CTA handles 2 k's; full g_x staged in 187.5KB smem;
// fc1_w (6.1MB) is the only DRAM traffic, read exactly once.
__global__ __launch_bounds__(256) void kC(const float* __restrict__ fw,
                                          const float* __restrict__ fb,
                                          float* __restrict__ out) {
    extern __shared__ float sx[];          // [8][6000]
    __shared__ float part[8][8];           // [warp][batch]

    int tid = threadIdx.x;
    int lane = tid & 31;
    int wid = tid >> 5;

    // Stage g_x (48000 floats = 12000 float4)
    {
        const float4* gp = reinterpret_cast<const float4*>(g_x);
        float4* sp = reinterpret_cast<float4*>(sx);
        for (int q = tid; q < (NB * KM) / 4; q += 256) sp[q] = gp[q];
    }
    __syncthreads();

    int kl = wid >> 2;                     // 0..1  (k within CTA)
    int quarter = wid & 3;                 // m-quarter
    int k = blockIdx.x * 2 + kl;
    const float4* wr = reinterpret_cast<const float4*>(fw + (size_t)k * KM) + quarter * (KM / 16);
    int base_m4 = quarter * (KM / 16);     // float4 offset within a batch row (375)

    float acc[8];
#pragma unroll
    for (int b = 0; b < 8; b++) acc[b] = 0.f;

    // 375 float4 per (k,quarter); lanes stride 32
    for (int q = lane; q < KM / 16; q += 32) {
        float4 wv = __ldcs(&wr[q]);
#pragma unroll
        for (int b = 0; b < 8; b++) {
            float4 xv = reinterpret_cast<const float4*>(sx)[b * (KM / 4) + base_m4 + q];
            acc[b] = fmaf(wv.x, xv.x, acc[b]);
            acc[b] = fmaf(wv.y, xv.y, acc[b]);
            acc[b] = fmaf(wv.z, xv.z, acc[b]);
            acc[b] = fmaf(wv.w, xv.w, acc[b]);
        }
    }

#pragma unroll
    for (int b = 0; b < 8; b++)
#pragma unroll
        for (int o = 16; o; o >>= 1)
            acc[b] += __shfl_xor_sync(~0u, acc[b], o);

    if (lane == 0) {
#pragma unroll
        for (int b = 0; b < 8; b++) part[wid][b] = acc[b];
    }
    __syncthreads();

    // 16 outputs per CTA: tid = kl*8 + b
    if (tid < 16) {
        int okl = tid >> 3;
        int b = tid & 7;
        int ok = blockIdx.x * 2 + okl;
        float s = part[4 * okl][b] + part[4 * okl + 1][b] +
                  part[4 * okl + 2][b] + part[4 * okl + 3][b] + fb[ok];
        out[(size_t)b * NHID + ok] = s;
    }
}

extern "C" void kernel_launch(void* const* d_in, const int* in_sizes, int n_in,
                              void* d_out, int out_size) {
    const float* emb   = (const float*)d_in[0];
    const float* W     = (const float*)d_in[1];
    const float* a     = (const float*)d_in[2];
    const float* fc1_w = (const float*)d_in[3];
    const float* fc1_b = (const float*)d_in[4];
    const int*   adj   = (const int*)d_in[5];
    float* out = (float*)d_out;

    cudaFuncSetAttribute(kC, cudaFuncAttributeMaxDynamicSharedMemorySize,
                         NB * KM * (int)sizeof(float));

    kA<<<63, 256>>>(emb, W, a);
    kB<<<125, 256>>>(adj);
    kC<<<NHID / 2, 256, NB * KM * sizeof(float)>>>(fc1_w, fc1_b, out);
}

// round 6
// speedup vs baseline: 1.0390x; 1.0390x over previous
#include <cuda_runtime.h>

#define NE 2000
#define NB 8
#define NHID 256
#define ALPHA 0.2f
#define MASKF 9e-15f
#define L2E 1.4426950408889634f
#define KM (NE * 3)          // 6000
#define NCTA 128
#define NWARPS (NCTA * 8)    // 1024

// Device scratch (no allocations allowed)
__device__ float g_s2[NE];
__device__ float g_h0[NE];
__device__ float g_h1[NE];
__device__ float g_h2[NE];
__device__ float g_s1[NE];
__device__ float g_x[NB * KM];   // elu(h_prime) flattened [b][i*3+d]

// Grid barrier state (self-resetting; safe across graph replays)
__device__ unsigned g_bar_cnt;
__device__ volatile unsigned g_bar_gen;

__device__ __forceinline__ float ex2f(float x) {
    float y;
    asm("ex2.approx.ftz.f32 %0, %1;" : "=f"(y) : "f"(x));
    return y;
}

// Device-wide barrier. All NCTA CTAs are resident (1 CTA/SM, 187.5KB smem).
__device__ __forceinline__ void grid_barrier() {
    __threadfence();                 // order this thread's prior writes (gpu scope)
    __syncthreads();
    if (threadIdx.x == 0) {
        unsigned my = g_bar_gen;
        if (atomicAdd(&g_bar_cnt, 1u) == NCTA - 1) {
            g_bar_cnt = 0;
            __threadfence();
            g_bar_gen = my + 1;
        } else {
            while (g_bar_gen == my) { __nanosleep(64); }
        }
    }
    __syncthreads();
}

__global__ __launch_bounds__(256, 1) void kF(const float* __restrict__ emb,
                                             const float* __restrict__ W,
                                             const float* __restrict__ a,
                                             const int*   __restrict__ adj,
                                             const float* __restrict__ fw,
                                             const float* __restrict__ fb,
                                             float* __restrict__ out) {
    extern __shared__ float sx[];          // phase B: 4 tables of 2000; phase C: g_x [8][6000]
    __shared__ float redbuf[8];
    __shared__ float part[8][8];

    int tid = threadIdx.x;
    int lane = tid & 31;
    int wid = tid >> 5;
    int gw = blockIdx.x * 8 + wid;         // global warp id 0..1023

    // ================= Phase A: h = emb@W ; s1 ; s2 =================
    for (int r = gw; r < NE; r += NWARPS) {
        float e0 = __ldg(&emb[(size_t)r * 64 + lane]);
        float e1 = __ldg(&emb[(size_t)r * 64 + 32 + lane]);
        float w00 = __ldg(&W[lane * 3 + 0]), w10 = __ldg(&W[(lane + 32) * 3 + 0]);
        float w01 = __ldg(&W[lane * 3 + 1]), w11 = __ldg(&W[(lane + 32) * 3 + 1]);
        float w02 = __ldg(&W[lane * 3 + 2]), w12 = __ldg(&W[(lane + 32) * 3 + 2]);
        float h0 = fmaf(e0, w00, e1 * w10);
        float h1 = fmaf(e0, w01, e1 * w11);
        float h2 = fmaf(e0, w02, e1 * w12);
#pragma unroll
        for (int o = 16; o; o >>= 1) {
            h0 += __shfl_xor_sync(~0u, h0, o);
            h1 += __shfl_xor_sync(~0u, h1, o);
            h2 += __shfl_xor_sync(~0u, h2, o);
        }
        if (lane == 0) {
            g_h0[r] = h0; g_h1[r] = h1; g_h2[r] = h2;
            g_s1[r] = h0 * __ldg(&a[0]) + h1 * __ldg(&a[1]) + h2 * __ldg(&a[2]);
            g_s2[r] = h0 * __ldg(&a[3]) + h1 * __ldg(&a[4]) + h2 * __ldg(&a[5]);
        }
    }

    grid_barrier();

    // ================= Phase B: masked softmax + aggregation + ELU =================
    float* ss2 = sx;
    float* sh0 = sx + NE;
    float* sh1 = sx + 2 * NE;
    float* sh2 = sx + 3 * NE;

    float mx = -1e30f;
    for (int q = tid; q < NE / 4; q += 256) {
        float4 v2 = __ldcg(reinterpret_cast<const float4*>(g_s2) + q);
        reinterpret_cast<float4*>(ss2)[q] = v2;
        reinterpret_cast<float4*>(sh0)[q] = __ldcg(reinterpret_cast<const float4*>(g_h0) + q);
        reinterpret_cast<float4*>(sh1)[q] = __ldcg(reinterpret_cast<const float4*>(g_h1) + q);
        reinterpret_cast<float4*>(sh2)[q] = __ldcg(reinterpret_cast<const float4*>(g_h2) + q);
        mx = fmaxf(fmaxf(fmaxf(mx, v2.x), fmaxf(v2.y, v2.z)), v2.w);
    }
#pragma unroll
    for (int o = 16; o; o >>= 1) mx = fmaxf(mx, __shfl_xor_sync(~0u, mx, o));
    if (lane == 0) redbuf[wid] = mx;
    __syncthreads();
    float s2max = redbuf[0];
#pragma unroll
    for (int w = 1; w < 8; w++) s2max = fmaxf(s2max, redbuf[w]);

#define PROC_K(COMP) do {                                                    \
        float t  = s1i + s2v.COMP;                                           \
        float e  = fmaxf(t, ALPHA * t);                                      \
        float wf = ex2f(fmaf(e, L2E, negc));                                 \
        float hj0 = h0v.COMP, hj1 = h1v.COMP, hj2 = h2v.COMP;                \
        _Pragma("unroll")                                                    \
        for (int b = 0; b < 8; b++) {                                        \
            float w = (av[b].COMP != 0) ? wf : w0;                           \
            Zb[b] += w;                                                      \
            A0[b] = fmaf(w, hj0, A0[b]);                                     \
            A1[b] = fmaf(w, hj1, A1[b]);                                     \
            A2[b] = fmaf(w, hj2, A2[b]);                                     \
        }                                                                    \
    } while (0)

#pragma unroll 1
    for (int ii = 0; ii < 2; ii++) {
        int i = gw + ii * NWARPS;
        if (i >= NE) break;
        float s1i = __ldcg(&g_s1[i]);
        float ts = s1i + s2max;
        float c = fmaxf(fmaxf(ts, ALPHA * ts), MASKF);   // valid softmax shift
        float negc = -c * L2E;
        float w0 = ex2f(fmaf(MASKF, L2E, negc));         // weight of masked entries

        const int* base = adj + (size_t)i * NE;

        float Zb[8], A0[8], A1[8], A2[8];
#pragma unroll
        for (int b = 0; b < 8; b++) { Zb[b] = 0.f; A0[b] = 0.f; A1[b] = 0.f; A2[b] = 0.f; }

#pragma unroll 2
        for (int it = 0; it < 15; it++) {
            int j0 = it * 128 + lane * 4;
            int4 av[8];
#pragma unroll
            for (int b = 0; b < 8; b++)
                av[b] = __ldcs(reinterpret_cast<const int4*>(base + (size_t)b * NE * NE + j0));
            float4 s2v = *reinterpret_cast<const float4*>(&ss2[j0]);
            float4 h0v = *reinterpret_cast<const float4*>(&sh0[j0]);
            float4 h1v = *reinterpret_cast<const float4*>(&sh1[j0]);
            float4 h2v = *reinterpret_cast<const float4*>(&sh2[j0]);
            PROC_K(x); PROC_K(y); PROC_K(z); PROC_K(w);
        }
        if (lane < 20) {       // j0 in [1920, 2000)
            int j0 = 1920 + lane * 4;
            int4 av[8];
#pragma unroll
            for (int b = 0; b < 8; b++)
                av[b] = __ldcs(reinterpret_cast<const int4*>(base + (size_t)b * NE * NE + j0));
            float4 s2v = *reinterpret_cast<const float4*>(&ss2[j0]);
            float4 h0v = *reinterpret_cast<const float4*>(&sh0[j0]);
            float4 h1v = *reinterpret_cast<const float4*>(&sh1[j0]);
            float4 h2v = *reinterpret_cast<const float4*>(&sh2[j0]);
            PROC_K(x); PROC_K(y); PROC_K(z); PROC_K(w);
        }

#pragma unroll
        for (int b = 0; b < 8; b++) {
#pragma unroll
            for (int o = 16; o; o >>= 1) {
                Zb[b] += __shfl_xor_sync(~0u, Zb[b], o);
                A0[b] += __shfl_xor_sync(~0u, A0[b], o);
                A1[b] += __shfl_xor_sync(~0u, A1[b], o);
                A2[b] += __shfl_xor_sync(~0u, A2[b], o);
            }
        }

        if (lane == 0) {
#pragma unroll
            for (int b = 0; b < 8; b++) {
                float inv = 1.0f / Zb[b];
                float p0 = A0[b] * inv;
                float p1 = A1[b] * inv;
                float p2 = A2[b] * inv;
                float x0 = (p0 > 0.f) ? p0 : expm1f(p0);
                float x1 = (p1 > 0.f) ? p1 : expm1f(p1);
                float x2 = (p2 > 0.f) ? p2 : expm1f(p2);
                float* xp = g_x + (size_t)b * KM + (size_t)i * 3;
                xp[0] = x0; xp[1] = x1; xp[2] = x2;
            }
        }
    }
#undef PROC_K

    grid_barrier();

    // ================= Phase C: out[b,k] = x[b,:] . fw[k,:] + fb[k] =================
    // Stage full g_x (48000 floats = 187.5KB) into smem; each CTA handles 2 k's.
    for (int q = tid; q < (NB * KM) / 4; q += 256)
        reinterpret_cast<float4*>(sx)[q] = __ldcg(reinterpret_cast<const float4*>(g_x) + q);
    __syncthreads();

    int kl = wid >> 2;                     // 0..1
    int quarter = wid & 3;
    int k = blockIdx.x * 2 + kl;
    const float4* wr = reinterpret_cast<const float4*>(fw + (size_t)k * KM) + quarter * (KM / 16);
    int base_m4 = quarter * (KM / 16);     // 375

    float acc[8];
#pragma unroll
    for (int b = 0; b < 8; b++) acc[b] = 0.f;

    for (int q = lane; q < KM / 16; q += 32) {
        float4 wv = __ldcs(&wr[q]);
#pragma unroll
        for (int b = 0; b < 8; b++) {
            float4 xv = reinterpret_cast<const float4*>(sx)[b * (KM / 4) + base_m4 + q];
            acc[b] = fmaf(wv.x, xv.x, acc[b]);
            acc[b] = fmaf(wv.y, xv.y, acc[b]);
            acc[b] = fmaf(wv.z, xv.z, acc[b]);
            acc[b] = fmaf(wv.w, xv.w, acc[b]);
        }
    }

#pragma unroll
    for (int b = 0; b < 8; b++)
#pragma unroll
        for (int o = 16; o; o >>= 1)
            acc[b] += __shfl_xor_sync(~0u, acc[b], o);

    if (lane == 0) {
#pragma unroll
        for (int b = 0; b < 8; b++) part[wid][b] = acc[b];
    }
    __syncthreads();

    if (tid < 16) {
        int okl = tid >> 3;
        int b = tid & 7;
        int ok = blockIdx.x * 2 + okl;
        float s = part[4 * okl][b] + part[4 * okl + 1][b] +
                  part[4 * okl + 2][b] + part[4 * okl + 3][b] + fb[ok];
        out[(size_t)b * NHID + ok] = s;
    }
}

extern "C" void kernel_launch(void* const* d_in, const int* in_sizes, int n_in,
                              void* d_out, int out_size) {
    const float* emb   = (const float*)d_in[0];
    const float* W     = (const float*)d_in[1];
    const float* a     = (const float*)d_in[2];
    const float* fc1_w = (const float*)d_in[3];
    const float* fc1_b = (const float*)d_in[4];
    const int*   adj   = (const int*)d_in[5];
    float* out = (float*)d_out;

    cudaFuncSetAttribute(kF, cudaFuncAttributeMaxDynamicSharedMemorySize,
                         NB * KM * (int)sizeof(float));

    kF<<<NCTA, 256, NB * KM * sizeof(float)>>>(emb, W, a, adj, fc1_w, fc1_b, out);
}

// round 8
// speedup vs baseline: 1.3628x; 1.3117x over previous
#include <cuda_runtime.h>

#define NE 2000
#define NB 8
#define NHID 256
#define ALPHA 0.2f
#define MASKF 9e-15f
#define L2E 1.4426950408889634f
#define KM (NE * 3)          // 6000
#define NCTA 128
#define NTHR 512
#define WPB 16               // warps per block
#define NWARPS (NCTA * WPB)  // 2048

// Device scratch (no allocations allowed)
__device__ float g_s2[NE];
__device__ float g_h0[NE];
__device__ float g_h1[NE];
__device__ float g_h2[NE];
__device__ float g_s1[NE];
__device__ float g_x[NB * KM];   // elu(h_prime) flattened [b][i*3+d]

// Grid barrier state (self-resetting; safe across graph replays)
__device__ unsigned g_bar_cnt;
__device__ volatile unsigned g_bar_gen;

__device__ __forceinline__ float ex2f(float x) {
    float y;
    asm("ex2.approx.ftz.f32 %0, %1;" : "=f"(y) : "f"(x));
    return y;
}

// Device-wide barrier. All NCTA CTAs are resident (1 CTA/SM via 187.5KB smem).
__device__ __forceinline__ void grid_barrier() {
    __threadfence();
    __syncthreads();
    if (threadIdx.x == 0) {
        unsigned my = g_bar_gen;
        if (atomicAdd(&g_bar_cnt, 1u) == NCTA - 1) {
            g_bar_cnt = 0;
            __threadfence();
            g_bar_gen = my + 1;
        } else {
            while (g_bar_gen == my) { __nanosleep(64); }
        }
    }
    __syncthreads();
}

__global__ __launch_bounds__(NTHR, 1) void kF(const float* __restrict__ emb,
                                              const float* __restrict__ W,
                                              const float* __restrict__ a,
                                              const int*   __restrict__ adj,
                                              const float* __restrict__ fw,
                                              const float* __restrict__ fb,
                                              float* __restrict__ out) {
    extern __shared__ float sx[];          // phase B: 4 tables of 2000; phase C: g_x [8][6000]
    __shared__ float redbuf[WPB];
    __shared__ float part[WPB][8];

    int tid = threadIdx.x;
    int lane = tid & 31;
    int wid = tid >> 5;
    int gw = blockIdx.x * WPB + wid;       // global warp id 0..2047

    // ================= Phase A: h = emb@W ; s1 ; s2 =================
    if (gw < NE) {
        int r = gw;
        float e0 = __ldg(&emb[(size_t)r * 64 + lane]);
        float e1 = __ldg(&emb[(size_t)r * 64 + 32 + lane]);
        float w00 = __ldg(&W[lane * 3 + 0]), w10 = __ldg(&W[(lane + 32) * 3 + 0]);
        float w01 = __ldg(&W[lane * 3 + 1]), w11 = __ldg(&W[(lane + 32) * 3 + 1]);
        float w02 = __ldg(&W[lane * 3 + 2]), w12 = __ldg(&W[(lane + 32) * 3 + 2]);
        float h0 = fmaf(e0, w00, e1 * w10);
        float h1 = fmaf(e0, w01, e1 * w11);
        float h2 = fmaf(e0, w02, e1 * w12);
#pragma unroll
        for (int o = 16; o; o >>= 1) {
            h0 += __shfl_xor_sync(~0u, h0, o);
            h1 += __shfl_xor_sync(~0u, h1, o);
            h2 += __shfl_xor_sync(~0u, h2, o);
        }
        if (lane == 0) {
            g_h0[r] = h0; g_h1[r] = h1; g_h2[r] = h2;
            g_s1[r] = h0 * __ldg(&a[0]) + h1 * __ldg(&a[1]) + h2 * __ldg(&a[2]);
            g_s2[r] = h0 * __ldg(&a[3]) + h1 * __ldg(&a[4]) + h2 * __ldg(&a[5]);
        }
    }

    grid_barrier();

    // ================= Phase B: masked softmax + aggregation + ELU =================
    float* ss2 = sx;
    float* sh0 = sx + NE;
    float* sh1 = sx + 2 * NE;
    float* sh2 = sx + 3 * NE;

    float mx = -1e30f;
    for (int q = tid; q < NE / 4; q += NTHR) {
        float4 v2 = __ldcg(reinterpret_cast<const float4*>(g_s2) + q);
        reinterpret_cast<float4*>(ss2)[q] = v2;
        reinterpret_cast<float4*>(sh0)[q] = __ldcg(reinterpret_cast<const float4*>(g_h0) + q);
        reinterpret_cast<float4*>(sh1)[q] = __ldcg(reinterpret_cast<const float4*>(g_h1) + q);
        reinterpret_cast<float4*>(sh2)[q] = __ldcg(reinterpret_cast<const float4*>(g_h2) + q);
        mx = fmaxf(fmaxf(fmaxf(mx, v2.x), fmaxf(v2.y, v2.z)), v2.w);
    }
#pragma unroll
    for (int o = 16; o; o >>= 1) mx = fmaxf(mx, __shfl_xor_sync(~0u, mx, o));
    if (lane == 0) redbuf[wid] = mx;
    __syncthreads();
    float s2max = redbuf[0];
#pragma unroll
    for (int w = 1; w < WPB; w++) s2max = fmaxf(s2max, redbuf[w]);

#define PROC_K(COMP) do {                                                    \
        float t  = s1i + s2v.COMP;                                           \
        float e  = fmaxf(t, ALPHA * t);                                      \
        float wf = ex2f(fmaf(e, L2E, negc));                                 \
        float hj0 = h0v.COMP, hj1 = h1v.COMP, hj2 = h2v.COMP;                \
        _Pragma("unroll")                                                    \
        for (int b = 0; b < 8; b++) {                                        \
            float w = (av[b].COMP != 0) ? wf : w0;                           \
            Zb[b] += w;                                                      \
            A0[b] = fmaf(w, hj0, A0[b]);                                     \
            A1[b] = fmaf(w, hj1, A1[b]);                                     \
            A2[b] = fmaf(w, hj2, A2[b]);                                     \
        }                                                                    \
    } while (0)

    if (gw < NE) {
        int i = gw;
        float s1i = __ldcg(&g_s1[i]);
        float ts = s1i + s2max;
        float c = fmaxf(fmaxf(ts, ALPHA * ts), MASKF);   // valid softmax shift
        float negc = -c * L2E;
        float w0 = ex2f(fmaf(MASKF, L2E, negc));         // weight of masked entries

        const int* base = adj + (size_t)i * NE;

        float Zb[8], A0[8], A1[8], A2[8];
#pragma unroll
        for (int b = 0; b < 8; b++) { Zb[b] = 0.f; A0[b] = 0.f; A1[b] = 0.f; A2[b] = 0.f; }

#pragma unroll 2
        for (int it = 0; it < 15; it++) {
            int j0 = it * 128 + lane * 4;
            int4 av[8];
#pragma unroll
            for (int b = 0; b < 8; b++)
                av[b] = __ldcs(reinterpret_cast<const int4*>(base + (size_t)b * NE * NE + j0));
            float4 s2v = *reinterpret_cast<const float4*>(&ss2[j0]);
            float4 h0v = *reinterpret_cast<const float4*>(&sh0[j0]);
            float4 h1v = *reinterpret_cast<const float4*>(&sh1[j0]);
            float4 h2v = *reinterpret_cast<const float4*>(&sh2[j0]);
            PROC_K(x); PROC_K(y); PROC_K(z); PROC_K(w);
        }
        if (lane < 20) {       // j0 in [1920, 2000)
            int j0 = 1920 + lane * 4;
            int4 av[8];
#pragma unroll
            for (int b = 0; b < 8; b++)
                av[b] = __ldcs(reinterpret_cast<const int4*>(base + (size_t)b * NE * NE + j0));
            float4 s2v = *reinterpret_cast<const float4*>(&ss2[j0]);
            float4 h0v = *reinterpret_cast<const float4*>(&sh0[j0]);
            float4 h1v = *reinterpret_cast<const float4*>(&sh1[j0]);
            float4 h2v = *reinterpret_cast<const float4*>(&sh2[j0]);
            PROC_K(x); PROC_K(y); PROC_K(z); PROC_K(w);
        }

#pragma unroll
        for (int b = 0; b < 8; b++) {
#pragma unroll
            for (int o = 16; o; o >>= 1) {
                Zb[b] += __shfl_xor_sync(~0u, Zb[b], o);
                A0[b] += __shfl_xor_sync(~0u, A0[b], o);
                A1[b] += __shfl_xor_sync(~0u, A1[b], o);
                A2[b] += __shfl_xor_sync(~0u, A2[b], o);
            }
        }

        if (lane == 0) {
#pragma unroll
            for (int b = 0; b < 8; b++) {
                float inv = 1.0f / Zb[b];
                float p0 = A0[b] * inv;
                float p1 = A1[b] * inv;
                float p2 = A2[b] * inv;
                float x0 = (p0 > 0.f) ? p0 : expm1f(p0);
                float x1 = (p1 > 0.f) ? p1 : expm1f(p1);
                float x2 = (p2 > 0.f) ? p2 : expm1f(p2);
                float* xp = g_x + (size_t)b * KM + (size_t)i * 3;
                xp[0] = x0; xp[1] = x1; xp[2] = x2;
            }
        }
    }
#undef PROC_K

    grid_barrier();

    // ================= Phase C: out[b,k] = x[b,:] . fw[k,:] + fb[k] =================
    // Stage full g_x (48000 floats = 187.5KB) into smem; each CTA handles 2 k's,
    // 8 warps per k. fc1_w (6.1MB) is the only DRAM traffic, read exactly once.
    for (int q = tid; q < (NB * KM) / 4; q += NTHR)
        reinterpret_cast<float4*>(sx)[q] = __ldcg(reinterpret_cast<const float4*>(g_x) + q);
    __syncthreads();

    int kl = wid >> 3;                     // 0..1
    int eighth = wid & 7;
    int k = blockIdx.x * 2 + kl;
    const float4* wr = reinterpret_cast<const float4*>(fw + (size_t)k * KM);

    float acc[8];
#pragma unroll
    for (int b = 0; b < 8; b++) acc[b] = 0.f;

    // 1500 float4 per k, 8 warps stride 256
    for (int q = eighth * 32 + lane; q < KM / 4; q += 256) {
        float4 wv = __ldcs(&wr[q]);
#pragma unroll
        for (int b = 0; b < 8; b++) {
            float4 xv = reinterpret_cast<const float4*>(sx)[b * (KM / 4) + q];
            acc[b] = fmaf(wv.x, xv.x, acc[b]);
            acc[b] = fmaf(wv.y, xv.y, acc[b]);
            acc[b] = fmaf(wv.z, xv.z, acc[b]);
            acc[b] = fmaf(wv.w, xv.w, acc[b]);
        }
    }

#pragma unroll
    for (int b = 0; b < 8; b++)
#pragma unroll
        for (int o = 16; o; o >>= 1)
            acc[b] += __shfl_xor_sync(~0u, acc[b], o);

    if (lane == 0) {
#pragma unroll
        for (int b = 0; b < 8; b++) part[wid][b] = acc[b];
    }
    __syncthreads();

    if (tid < 16) {
        int okl = tid >> 3;
        int b = tid & 7;
        int ok = blockIdx.x * 2 + okl;
        float s = fb[ok];
#pragma unroll
        for (int w = 0; w < 8; w++) s += part[okl * 8 + w][b];
        out[(size_t)b * NHID + ok] = s;
    }
}

extern "C" void kernel_launch(void* const* d_in, const int* in_sizes, int n_in,
                              void* d_out, int out_size) {
    const float* emb   = (const float*)d_in[0];
    const float* W     = (const float*)d_in[1];
    const float* a     = (const float*)d_in[2];
    const float* fc1_w = (const float*)d_in[3];
    const float* fc1_b = (const float*)d_in[4];
    const int*   adj   = (const int*)d_in[5];
    float* out = (float*)d_out;

    cudaFuncSetAttribute(kF, cudaFuncAttributeMaxDynamicSharedMemorySize,
                         NB * KM * (int)sizeof(float));

    kF<<<NCTA, NTHR, NB * KM * sizeof(float)>>>(emb, W, a, adj, fc1_w, fc1_b, out);
}

// round 10
// speedup vs baseline: 1.3639x; 1.0008x over previous
#include <cuda_runtime.h>

#define NE 2000
#define NB 8
#define NHID 256
#define ALPHA 0.2f
#define MASKF 9e-15f
#define L2E 1.4426950408889634f
#define KM (NE * 3)          // 6000
#define NCTA 148
#define NTHR 512
#define WPB 16               // warps per block
#define NWARPS (NCTA * WPB)  // 2368

// Device scratch (no allocations allowed)
__device__ float g_s2[NE];
__device__ float g_h0[NE];
__device__ float g_h1[NE];
__device__ float g_h2[NE];
__device__ float g_s1[NE];
__device__ float g_x[NB * KM];   // elu(h_prime) flattened [b][i*3+d]

// Grid barrier state (self-resetting; safe across graph replays)
__device__ unsigned g_bar_cnt;
__device__ volatile unsigned g_bar_gen;

__device__ __forceinline__ float ex2f(float x) {
    float y;
    asm("ex2.approx.ftz.f32 %0, %1;" : "=f"(y) : "f"(x));
    return y;
}

// Device-wide barrier. All NCTA CTAs are resident (1 CTA/SM via 187.5KB smem, 148 SMs).
__device__ __forceinline__ void grid_barrier() {
    __threadfence();
    __syncthreads();
    if (threadIdx.x == 0) {
        unsigned my = g_bar_gen;
        if (atomicAdd(&g_bar_cnt, 1u) == NCTA - 1) {
            g_bar_cnt = 0;
            __threadfence();
            g_bar_gen = my + 1;
        } else {
            while (g_bar_gen == my) { __nanosleep(64); }
        }
    }
    __syncthreads();
}

__global__ __launch_bounds__(NTHR, 1) void kF(const float* __restrict__ emb,
                                              const float* __restrict__ W,
                                              const float* __restrict__ a,
                                              const int*   __restrict__ adj,
                                              const float* __restrict__ fw,
                                              const float* __restrict__ fb,
                                              float* __restrict__ out) {
    extern __shared__ float sx[];          // phase B: 4 tables of 2000; phase C: g_x [8][6000]
    __shared__ float redbuf[WPB];
    __shared__ float part[WPB][8];

    int tid = threadIdx.x;
    int lane = tid & 31;
    int wid = tid >> 5;
    int gw = blockIdx.x * WPB + wid;       // global warp id 0..2367

    // ================= Phase A: h = emb@W ; s1 ; s2 =================
    if (gw < NE) {
        int r = gw;
        float e0 = __ldg(&emb[(size_t)r * 64 + lane]);
        float e1 = __ldg(&emb[(size_t)r * 64 + 32 + lane]);
        float w00 = __ldg(&W[lane * 3 + 0]), w10 = __ldg(&W[(lane + 32) * 3 + 0]);
        float w01 = __ldg(&W[lane * 3 + 1]), w11 = __ldg(&W[(lane + 32) * 3 + 1]);
        float w02 = __ldg(&W[lane * 3 + 2]), w12 = __ldg(&W[(lane + 32) * 3 + 2]);
        float h0 = fmaf(e0, w00, e1 * w10);
        float h1 = fmaf(e0, w01, e1 * w11);
        float h2 = fmaf(e0, w02, e1 * w12);
#pragma unroll
        for (int o = 16; o; o >>= 1) {
            h0 += __shfl_xor_sync(~0u, h0, o);
            h1 += __shfl_xor_sync(~0u, h1, o);
            h2 += __shfl_xor_sync(~0u, h2, o);
        }
        if (lane == 0) {
            g_h0[r] = h0; g_h1[r] = h1; g_h2[r] = h2;
            g_s1[r] = h0 * __ldg(&a[0]) + h1 * __ldg(&a[1]) + h2 * __ldg(&a[2]);
            g_s2[r] = h0 * __ldg(&a[3]) + h1 * __ldg(&a[4]) + h2 * __ldg(&a[5]);
        }
    }

    grid_barrier();

    // ================= Phase B: masked softmax + aggregation + ELU =================
    float* ss2 = sx;
    float* sh0 = sx + NE;
    float* sh1 = sx + 2 * NE;
    float* sh2 = sx + 3 * NE;

    float mx = -1e30f;
    for (int q = tid; q < NE / 4; q += NTHR) {
        float4 v2 = __ldcg(reinterpret_cast<const float4*>(g_s2) + q);
        reinterpret_cast<float4*>(ss2)[q] = v2;
        reinterpret_cast<float4*>(sh0)[q] = __ldcg(reinterpret_cast<const float4*>(g_h0) + q);
        reinterpret_cast<float4*>(sh1)[q] = __ldcg(reinterpret_cast<const float4*>(g_h1) + q);
        reinterpret_cast<float4*>(sh2)[q] = __ldcg(reinterpret_cast<const float4*>(g_h2) + q);
        mx = fmaxf(fmaxf(fmaxf(mx, v2.x), fmaxf(v2.y, v2.z)), v2.w);
    }
#pragma unroll
    for (int o = 16; o; o >>= 1) mx = fmaxf(mx, __shfl_xor_sync(~0u, mx, o));
    if (lane == 0) redbuf[wid] = mx;
    __syncthreads();
    float s2max = redbuf[0];
#pragma unroll
    for (int w = 1; w < WPB; w++) s2max = fmaxf(s2max, redbuf[w]);

    if (gw < NE) {
        int i = gw;
        float s1i = __ldcg(&g_s1[i]);
        float ts = s1i + s2max;
        float c = fmaxf(fmaxf(ts, ALPHA * ts), MASKF);   // valid softmax shift
        float negc = -c * L2E;
        float w0 = ex2f(fmaf(MASKF, L2E, negc));         // weight of masked entries

        const int* bp[8];
#pragma unroll
        for (int b = 0; b < 8; b++)
            bp[b] = adj + (size_t)b * NE * NE + (size_t)i * NE;

        float Zb[8], A0[8], A1[8], A2[8];
#pragma unroll
        for (int b = 0; b < 8; b++) { Zb[b] = 0.f; A0[b] = 0.f; A1[b] = 0.f; A2[b] = 0.f; }

        // Software pipeline: prologue loads batches 0-3 of iteration 0.
        int4 cur[4];
#pragma unroll
        for (int b = 0; b < 4; b++)
            cur[b] = __ldcs(reinterpret_cast<const int4*>(bp[b] + lane * 4));

#pragma unroll 2
        for (int it = 0; it < 15; it++) {
            int j0 = it * 128 + lane * 4;

            // Issue loads for batches 4-7 of this iteration (overlap half-A compute)
            int4 hi[4];
#pragma unroll
            for (int b = 0; b < 4; b++)
                hi[b] = __ldcs(reinterpret_cast<const int4*>(bp[b + 4] + j0));

            float4 s2v = *reinterpret_cast<const float4*>(&ss2[j0]);
            float4 h0v = *reinterpret_cast<const float4*>(&sh0[j0]);
            float4 h1v = *reinterpret_cast<const float4*>(&sh1[j0]);
            float4 h2v = *reinterpret_cast<const float4*>(&sh2[j0]);

            float wfv[4];
#pragma unroll
            for (int cmp = 0; cmp < 4; cmp++) {
                float t = s1i + (&s2v.x)[cmp];
                float e = fmaxf(t, ALPHA * t);
                wfv[cmp] = ex2f(fmaf(e, L2E, negc));
            }

            // Half A: batches 0-3 using prefetched cur
#pragma unroll
            for (int cmp = 0; cmp < 4; cmp++) {
                float wf = wfv[cmp];
                float hj0 = (&h0v.x)[cmp], hj1 = (&h1v.x)[cmp], hj2 = (&h2v.x)[cmp];
#pragma unroll
                for (int b = 0; b < 4; b++) {
                    float w = ((&cur[b].x)[cmp] != 0) ? wf : w0;
                    Zb[b] += w;
                    A0[b] = fmaf(w, hj0, A0[b]);
                    A1[b] = fmaf(w, hj1, A1[b]);
                    A2[b] = fmaf(w, hj2, A2[b]);
                }
            }

            // Issue loads for batches 0-3 of NEXT iteration (overlap half-B compute).
            // Last iteration: clamp to j=lane*4 (in-bounds, result unused).
            int jn = (it < 14) ? j0 + 128 : lane * 4;
            int4 nxt[4];
#pragma unroll
            for (int b = 0; b < 4; b++)
                nxt[b] = __ldcs(reinterpret_cast<const int4*>(bp[b] + jn));

            // Half B: batches 4-7 using hi
#pragma unroll
            for (int cmp = 0; cmp < 4; cmp++) {
                float wf = wfv[cmp];
                float hj0 = (&h0v.x)[cmp], hj1 = (&h1v.x)[cmp], hj2 = (&h2v.x)[cmp];
#pragma unroll
                for (int b = 0; b < 4; b++) {
                    float w = ((&hi[b].x)[cmp] != 0) ? wf : w0;
                    Zb[b + 4] += w;
                    A0[b + 4] = fmaf(w, hj0, A0[b + 4]);
                    A1[b + 4] = fmaf(w, hj1, A1[b + 4]);
                    A2[b + 4] = fmaf(w, hj2, A2[b + 4]);
                }
            }

#pragma unroll
            for (int b = 0; b < 4; b++) cur[b] = nxt[b];
        }

        // Epilogue: j0 in [1920, 2000) -> lanes 0..19 (unpipelined)
        if (lane < 20) {
            int j0 = 1920 + lane * 4;
            int4 av[8];
#pragma unroll
            for (int b = 0; b < 8; b++)
                av[b] = __ldcs(reinterpret_cast<const int4*>(bp[b] + j0));
            float4 s2v = *reinterpret_cast<const float4*>(&ss2[j0]);
            float4 h0v = *reinterpret_cast<const float4*>(&sh0[j0]);
            float4 h1v = *reinterpret_cast<const float4*>(&sh1[j0]);
            float4 h2v = *reinterpret_cast<const float4*>(&sh2[j0]);
#pragma unroll
            for (int cmp = 0; cmp < 4; cmp++) {
                float t = s1i + (&s2v.x)[cmp];
                float e = fmaxf(t, ALPHA * t);
                float wf = ex2f(fmaf(e, L2E, negc));
                float hj0 = (&h0v.x)[cmp], hj1 = (&h1v.x)[cmp], hj2 = (&h2v.x)[cmp];
#pragma unroll
                for (int b = 0; b < 8; b++) {
                    float w = ((&av[b].x)[cmp] != 0) ? wf : w0;
                    Zb[b] += w;
                    A0[b] = fmaf(w, hj0, A0[b]);
                    A1[b] = fmaf(w, hj1, A1[b]);
                    A2[b] = fmaf(w, hj2, A2[b]);
                }
            }
        }

        // warp reductions (32 accumulators)
#pragma unroll
        for (int b = 0; b < 8; b++) {
#pragma unroll
            for (int o = 16; o; o >>= 1) {
                Zb[b] += __shfl_xor_sync(~0u, Zb[b], o);
                A0[b] += __shfl_xor_sync(~0u, A0[b], o);
                A1[b] += __shfl_xor_sync(~0u, A1[b], o);
                A2[b] += __shfl_xor_sync(~0u, A2[b], o);
            }
        }

        if (lane == 0) {
#pragma unroll
            for (int b = 0; b < 8; b++) {
                float inv = 1.0f / Zb[b];
                float p0 = A0[b] * inv;
                float p1 = A1[b] * inv;
                float p2 = A2[b] * inv;
                float x0 = (p0 > 0.f) ? p0 : expm1f(p0);
                float x1 = (p1 > 0.f) ? p1 : expm1f(p1);
                float x2 = (p2 > 0.f) ? p2 : expm1f(p2);
                float* xp = g_x + (size_t)b * KM + (size_t)i * 3;
                xp[0] = x0; xp[1] = x1; xp[2] = x2;
            }
        }
    }

    grid_barrier();

    // ================= Phase C: out[b,k] = x[b,:] . fw[k,:] + fb[k] =================
    // Stage full g_x (187.5KB) into smem. 256 outputs over 148 CTAs:
    // CTAs 0..107 take 2 k's (8 warps each), CTAs 108..147 take 1 k (16 warps).
    for (int q = tid; q < (NB * KM) / 4; q += NTHR)
        reinterpret_cast<float4*>(sx)[q] = __ldcg(reinterpret_cast<const float4*>(g_x) + q);
    __syncthreads();

    int cta = blockIdx.x;
    bool two = (cta < 108);
    int kstart = two ? 2 * cta : 216 + (cta - 108);
    int k = two ? (kstart + (wid >> 3)) : kstart;
    int qstart = two ? ((wid & 7) * 32 + lane) : (wid * 32 + lane);
    int qstep = two ? 256 : 512;

    const float4* wr = reinterpret_cast<const float4*>(fw + (size_t)k * KM);

    float acc[8];
#pragma unroll
    for (int b = 0; b < 8; b++) acc[b] = 0.f;

    for (int q = qstart; q < KM / 4; q += qstep) {
        float4 wv = __ldcs(&wr[q]);
#pragma unroll
        for (int b = 0; b < 8; b++) {
            float4 xv = reinterpret_cast<const float4*>(sx)[b * (KM / 4) + q];
            acc[b] = fmaf(wv.x, xv.x, acc[b]);
            acc[b] = fmaf(wv.y, xv.y, acc[b]);
            acc[b] = fmaf(wv.z, xv.z, acc[b]);
            acc[b] = fmaf(wv.w, xv.w, acc[b]);
        }
    }

#pragma unroll
    for (int b = 0; b < 8; b++)
#pragma unroll
        for (int o = 16; o; o >>= 1)
            acc[b] += __shfl_xor_sync(~0u, acc[b], o);

    if (lane == 0) {
#pragma unroll
        for (int b = 0; b < 8; b++) part[wid][b] = acc[b];
    }
    __syncthreads();

    if (two) {
        if (tid < 16) {
            int okl = tid >> 3;
            int b = tid & 7;
            int ok = kstart + okl;
            float s = fb[ok];
#pragma unroll
            for (int w = 0; w < 8; w++) s += part[okl * 8 + w][b];
            out[(size_t)b * NHID + ok] = s;
        }
    } else {
        if (tid < 8) {
            int b = tid;
            float s = fb[kstart];
#pragma unroll
            for (int w = 0; w < 16; w++) s += part[w][b];
            out[(size_t)b * NHID + kstart] = s;
        }
    }
}

extern "C" void kernel_launch(void* const* d_in, const int* in_sizes, int n_in,
                              void* d_out, int out_size) {
    const float* emb   = (const float*)d_in[0];
    const float* W     = (const float*)d_in[1];
    const float* a     = (const float*)d_in[2];
    const float* fc1_w = (const float*)d_in[3];
    const float* fc1_b = (const float*)d_in[4];
    const int*   adj   = (const int*)d_in[5];
    float* out = (float*)d_out;

    cudaFuncSetAttribute(kF, cudaFuncAttributeMaxDynamicSharedMemorySize,
                         NB * KM * (int)sizeof(float));

    kF<<<NCTA, NTHR, NB * KM * sizeof(float)>>>(emb, W, a, adj, fc1_w, fc1_b, out);
}

// round 13
// speedup vs baseline: 1.4387x; 1.0548x over previous
#include <cuda_runtime.h>

#define NE 2000
#define NB 8
#define NHID 256
#define ALPHA 0.2f
#define MASKF 9e-15f
#define L2E 1.4426950408889634f
#define KM (NE * 3)          // 6000
#define NCTA 148
#define NTHR 1024
#define WPB 32               // warps per block
#define NWARPS (NCTA * WPB)  // 4736

// Device scratch (no allocations allowed)
__device__ float g_s2[NE];
__device__ float g_h0[NE];
__device__ float g_h1[NE];
__device__ float g_h2[NE];
__device__ float g_s1[NE];
__device__ float g_x[NB * KM];   // elu(h_prime) flattened [b][i*3+d]

// Grid barrier state (self-resetting; safe across graph replays)
__device__ unsigned g_bar_cnt;
__device__ volatile unsigned g_bar_gen;

__device__ __forceinline__ float ex2f(float x) {
    float y;
    asm("ex2.approx.ftz.f32 %0, %1;" : "=f"(y) : "f"(x));
    return y;
}

// Device-wide barrier. All NCTA CTAs are resident (1 CTA/SM: 187.5KB smem + full RF).
__device__ __forceinline__ void grid_barrier() {
    __threadfence();
    __syncthreads();
    if (threadIdx.x == 0) {
        unsigned my = g_bar_gen;
        if (atomicAdd(&g_bar_cnt, 1u) == NCTA - 1) {
            g_bar_cnt = 0;
            __threadfence();
            g_bar_gen = my + 1;
        } else {
            while (g_bar_gen == my) { __nanosleep(64); }
        }
    }
    __syncthreads();
}

__global__ __launch_bounds__(NTHR, 1) void kF(const float* __restrict__ emb,
                                              const float* __restrict__ W,
                                              const float* __restrict__ a,
                                              const int*   __restrict__ adj,
                                              const float* __restrict__ fw,
                                              const float* __restrict__ fb,
                                              float* __restrict__ out) {
    extern __shared__ float sx[];          // phase B: 4 tables of 2000; phase C: g_x [8][6000]
    __shared__ float redbuf[WPB];
    __shared__ float part[WPB][8];

    int tid = threadIdx.x;
    int lane = tid & 31;
    int wid = tid >> 5;
    int gw = blockIdx.x * WPB + wid;       // global warp id 0..4735

    // ================= Phase A: h = emb@W ; s1 ; s2 =================
    if (gw < NE) {
        int r = gw;
        float e0 = __ldg(&emb[(size_t)r * 64 + lane]);
        float e1 = __ldg(&emb[(size_t)r * 64 + 32 + lane]);
        float w00 = __ldg(&W[lane * 3 + 0]), w10 = __ldg(&W[(lane + 32) * 3 + 0]);
        float w01 = __ldg(&W[lane * 3 + 1]), w11 = __ldg(&W[(lane + 32) * 3 + 1]);
        float w02 = __ldg(&W[lane * 3 + 2]), w12 = __ldg(&W[(lane + 32) * 3 + 2]);
        float h0 = fmaf(e0, w00, e1 * w10);
        float h1 = fmaf(e0, w01, e1 * w11);
        float h2 = fmaf(e0, w02, e1 * w12);
#pragma unroll
        for (int o = 16; o; o >>= 1) {
            h0 += __shfl_xor_sync(~0u, h0, o);
            h1 += __shfl_xor_sync(~0u, h1, o);
            h2 += __shfl_xor_sync(~0u, h2, o);
        }
        if (lane == 0) {
            g_h0[r] = h0; g_h1[r] = h1; g_h2[r] = h2;
            g_s1[r] = h0 * __ldg(&a[0]) + h1 * __ldg(&a[1]) + h2 * __ldg(&a[2]);
            g_s2[r] = h0 * __ldg(&a[3]) + h1 * __ldg(&a[4]) + h2 * __ldg(&a[5]);
        }
    }

    grid_barrier();

    // ================= Phase B: masked softmax + aggregation + ELU =================
    // One warp per (row i, batch-half) task: 4000 tasks over 4736 warps, one round.
    float* ss2 = sx;
    float* sh0 = sx + NE;
    float* sh1 = sx + 2 * NE;
    float* sh2 = sx + 3 * NE;

    float mx = -1e30f;
    for (int q = tid; q < NE / 4; q += NTHR) {
        float4 v2 = __ldcg(reinterpret_cast<const float4*>(g_s2) + q);
        reinterpret_cast<float4*>(ss2)[q] = v2;
        reinterpret_cast<float4*>(sh0)[q] = __ldcg(reinterpret_cast<const float4*>(g_h0) + q);
        reinterpret_cast<float4*>(sh1)[q] = __ldcg(reinterpret_cast<const float4*>(g_h1) + q);
        reinterpret_cast<float4*>(sh2)[q] = __ldcg(reinterpret_cast<const float4*>(g_h2) + q);
        mx = fmaxf(fmaxf(fmaxf(mx, v2.x), fmaxf(v2.y, v2.z)), v2.w);
    }
#pragma unroll
    for (int o = 16; o; o >>= 1) mx = fmaxf(mx, __shfl_xor_sync(~0u, mx, o));
    if (lane == 0) redbuf[wid] = mx;
    __syncthreads();
    float s2max = redbuf[0];
#pragma unroll
    for (int w = 1; w < WPB; w++) s2max = fmaxf(s2max, redbuf[w]);

    if (gw < 2 * NE) {
        int i  = gw >> 1;                  // row
        int b0 = (gw & 1) * 4;             // batch half: 0..3 or 4..7
        float s1i = __ldcg(&g_s1[i]);
        float ts = s1i + s2max;
        float c = fmaxf(fmaxf(ts, ALPHA * ts), MASKF);   // valid softmax shift
        float negc = -c * L2E;
        float w0 = ex2f(fmaf(MASKF, L2E, negc));         // weight of masked entries

        const int* bp[4];
#pragma unroll
        for (int b = 0; b < 4; b++)
            bp[b] = adj + (size_t)(b0 + b) * NE * NE + (size_t)i * NE;

        float Zb[4], A0[4], A1[4], A2[4];
#pragma unroll
        for (int b = 0; b < 4; b++) { Zb[b] = 0.f; A0[b] = 0.f; A1[b] = 0.f; A2[b] = 0.f; }

#pragma unroll 1
        for (int it = 0; it < 15; it++) {
            int j0 = it * 128 + lane * 4;
            int4 av[4];
#pragma unroll
            for (int b = 0; b < 4; b++)
                av[b] = __ldcs(reinterpret_cast<const int4*>(bp[b] + j0));
            float4 s2v = *reinterpret_cast<const float4*>(&ss2[j0]);
            float4 h0v = *reinterpret_cast<const float4*>(&sh0[j0]);
            float4 h1v = *reinterpret_cast<const float4*>(&sh1[j0]);
            float4 h2v = *reinterpret_cast<const float4*>(&sh2[j0]);
#pragma unroll
            for (int cmp = 0; cmp < 4; cmp++) {
                float t = s1i + (&s2v.x)[cmp];
                float e = fmaxf(t, ALPHA * t);
                float wf = ex2f(fmaf(e, L2E, negc));
                float hj0 = (&h0v.x)[cmp], hj1 = (&h1v.x)[cmp], hj2 = (&h2v.x)[cmp];
#pragma unroll
                for (int b = 0; b < 4; b++) {
                    float w = ((&av[b].x)[cmp] != 0) ? wf : w0;
                    Zb[b] += w;
                    A0[b] = fmaf(w, hj0, A0[b]);
                    A1[b] = fmaf(w, hj1, A1[b]);
                    A2[b] = fmaf(w, hj2, A2[b]);
                }
            }
        }

        // Epilogue: j0 in [1920, 2000) -> lanes 0..19
        if (lane < 20) {
            int j0 = 1920 + lane * 4;
            int4 av[4];
#pragma unroll
            for (int b = 0; b < 4; b++)
                av[b] = __ldcs(reinterpret_cast<const int4*>(bp[b] + j0));
            float4 s2v = *reinterpret_cast<const float4*>(&ss2[j0]);
            float4 h0v = *reinterpret_cast<const float4*>(&sh0[j0]);
            float4 h1v = *reinterpret_cast<const float4*>(&sh1[j0]);
            float4 h2v = *reinterpret_cast<const float4*>(&sh2[j0]);
#pragma unroll
            for (int cmp = 0; cmp < 4; cmp++) {
                float t = s1i + (&s2v.x)[cmp];
                float e = fmaxf(t, ALPHA * t);
                float wf = ex2f(fmaf(e, L2E, negc));
                float hj0 = (&h0v.x)[cmp], hj1 = (&h1v.x)[cmp], hj2 = (&h2v.x)[cmp];
#pragma unroll
                for (int b = 0; b < 4; b++) {
                    float w = ((&av[b].x)[cmp] != 0) ? wf : w0;
                    Zb[b] += w;
                    A0[b] = fmaf(w, hj0, A0[b]);
                    A1[b] = fmaf(w, hj1, A1[b]);
                    A2[b] = fmaf(w, hj2, A2[b]);
                }
            }
        }

        // warp reductions (16 accumulators)
#pragma unroll
        for (int b = 0; b < 4; b++) {
#pragma unroll
            for (int o = 16; o; o >>= 1) {
                Zb[b] += __shfl_xor_sync(~0u, Zb[b], o);
                A0[b] += __shfl_xor_sync(~0u, A0[b], o);
                A1[b] += __shfl_xor_sync(~0u, A1[b], o);
                A2[b] += __shfl_xor_sync(~0u, A2[b], o);
            }
        }

        if (lane == 0) {
#pragma unroll
            for (int b = 0; b < 4; b++) {
                float inv = 1.0f / Zb[b];
                float p0 = A0[b] * inv;
                float p1 = A1[b] * inv;
                float p2 = A2[b] * inv;
                float x0 = (p0 > 0.f) ? p0 : expm1f(p0);
                float x1 = (p1 > 0.f) ? p1 : expm1f(p1);
                float x2 = (p2 > 0.f) ? p2 : expm1f(p2);
                float* xp = g_x + (size_t)(b0 + b) * KM + (size_t)i * 3;
                xp[0] = x0; xp[1] = x1; xp[2] = x2;
            }
        }
    }

    grid_barrier();

    // ================= Phase C: out[b,k] = x[b,:] . fw[k,:] + fb[k] =================
    // Stage full g_x (187.5KB) into smem. 256 outputs over 148 CTAs:
    // CTAs 0..107 take 2 k's (16 warps each), CTAs 108..147 take 1 k (32 warps).
    for (int q = tid; q < (NB * KM) / 4; q += NTHR)
        reinterpret_cast<float4*>(sx)[q] = __ldcg(reinterpret_cast<const float4*>(g_x) + q);
    __syncthreads();

    int cta = blockIdx.x;
    bool two = (cta < 108);
    int kstart = two ? 2 * cta : 216 + (cta - 108);
    int k = two ? (kstart + (wid >> 4)) : kstart;
    int qstart = two ? ((wid & 15) * 32 + lane) : (wid * 32 + lane);
    int qstep = two ? 512 : 1024;

    const float4* wr = reinterpret_cast<const float4*>(fw + (size_t)k * KM);

    float acc[8];
#pragma unroll
    for (int b = 0; b < 8; b++) acc[b] = 0.f;

    for (int q = qstart; q < KM / 4; q += qstep) {
        float4 wv = __ldcs(&wr[q]);
#pragma unroll
        for (int b = 0; b < 8; b++) {
            float4 xv = reinterpret_cast<const float4*>(sx)[b * (KM / 4) + q];
            acc[b] = fmaf(wv.x, xv.x, acc[b]);
            acc[b] = fmaf(wv.y, xv.y, acc[b]);
            acc[b] = fmaf(wv.z, xv.z, acc[b]);
            acc[b] = fmaf(wv.w, xv.w, acc[b]);
        }
    }

#pragma unroll
    for (int b = 0; b < 8; b++)
#pragma unroll
        for (int o = 16; o; o >>= 1)
            acc[b] += __shfl_xor_sync(~0u, acc[b], o);

    if (lane == 0) {
#pragma unroll
        for (int b = 0; b < 8; b++) part[wid][b] = acc[b];
    }
    __syncthreads();

    if (two) {
        if (tid < 16) {
            int okl = tid >> 3;
            int b = tid & 7;
            int ok = kstart + okl;
            float s = fb[ok];
#pragma unroll
            for (int w = 0; w < 16; w++) s += part[okl * 16 + w][b];
            out[(size_t)b * NHID + ok] = s;
        }
    } else {
        if (tid < 8) {
            int b = tid;
            float s = fb[kstart];
#pragma unroll
            for (int w = 0; w < WPB; w++) s += part[w][b];
            out[(size_t)b * NHID + kstart] = s;
        }
    }
}

extern "C" void kernel_launch(void* const* d_in, const int* in_sizes, int n_in,
                              void* d_out, int out_size) {
    const float* emb   = (const float*)d_in[0];
    const float* W     = (const float*)d_in[1];
    const float* a     = (const float*)d_in[2];
    const float* fc1_w = (const float*)d_in[3];
    const float* fc1_b = (const float*)d_in[4];
    const int*   adj   = (const int*)d_in[5];
    float* out = (float*)d_out;

    cudaFuncSetAttribute(kF, cudaFuncAttributeMaxDynamicSharedMemorySize,
                         NB * KM * (int)sizeof(float));

    kF<<<NCTA, NTHR, NB * KM * sizeof(float)>>>(emb, W, a, adj, fc1_w, fc1_b, out);
}